// round 7
// baseline (speedup 1.0000x reference)
#include <cuda_runtime.h>

#define NN 100000
#define EE 1600000
#define DD 64
#define GG 64
#define OUTC 10
#define NB ((NN + 255) / 256)   // 391 scan blocks

// ---- scratch ----
__device__ int    g_is64;
__device__ int    g_batch[NN];
__device__ int    g_deg[NN];
__device__ int    g_cursor[NN];
__device__ int    g_rowstart[NN + 1];
__device__ int    g_bsum[NB];
__device__ int    g_bsum_sc[NB];
__device__ int    g_adj[EE];
__device__ float  g_inv_deg[NN];
__device__ float4 g_agg[(size_t)NN * (DD / 4)];
__device__ float4 g_h0 [(size_t)NN * (DD / 4)];
__device__ float4 g_h1 [(size_t)NN * (DD / 4)];
__device__ float  g_pool[GG * DD];

// ---------------- dtype detection ----------------
// Reference says int64, but JAX x64-off + harness policy typically delivers
// int32. View head as int64 pairs: genuine int64 indices (<2^31) have zero
// high words; random int32 index pairs do not.
__global__ void detect_kernel(const unsigned int* __restrict__ w) {
    int is64 = 1;
    for (int i = 0; i < 32; i++)
        if (w[2 * i + 1] != 0u) { is64 = 0; break; }
    g_is64 = is64;
}

__device__ __forceinline__ int load_idx(const void* p, size_t i, int is64) {
    return is64 ? (int)((const long long*)p)[i] : ((const int*)p)[i];
}

// ---------------- batch convert + zero ----------------
__global__ void prep_kernel(const void* __restrict__ bat) {
    int i = blockIdx.x * blockDim.x + threadIdx.x;
    if (i < NN) {
        g_batch[i]  = load_idx(bat, i, g_is64);
        g_deg[i]    = 0;
        g_cursor[i] = 0;
    }
}

// ---------------- CSR build (reads edge_index directly) ----------------
__global__ void deg_kernel(const void* __restrict__ ei) {
    int e = blockIdx.x * blockDim.x + threadIdx.x;
    if (e < EE) atomicAdd(&g_deg[load_idx(ei, (size_t)EE + e, g_is64)], 1);
}

__global__ void scan_block_kernel() {
    __shared__ int s[256];
    int tid = threadIdx.x;
    int i = blockIdx.x * 256 + tid;
    int v = (i < NN) ? g_deg[i] : 0;
    s[tid] = v;
    __syncthreads();
    #pragma unroll
    for (int off = 1; off < 256; off <<= 1) {
        int t = (tid >= off) ? s[tid - off] : 0;
        __syncthreads();
        s[tid] += t;
        __syncthreads();
    }
    if (i < NN) g_rowstart[i] = s[tid] - v;   // exclusive
    if (tid == 255) g_bsum[blockIdx.x] = s[255];
}

__global__ void scan_top_kernel() {
    __shared__ int s[512];
    int tid = threadIdx.x;
    int v = (tid < NB) ? g_bsum[tid] : 0;
    s[tid] = v;
    __syncthreads();
    #pragma unroll
    for (int off = 1; off < 512; off <<= 1) {
        int t = (tid >= off) ? s[tid - off] : 0;
        __syncthreads();
        s[tid] += t;
        __syncthreads();
    }
    if (tid < NB) g_bsum_sc[tid] = s[tid] - v;
}

__global__ void scan_add_kernel() {
    int i = blockIdx.x * 256 + threadIdx.x;
    if (i < NN) {
        g_rowstart[i] += g_bsum_sc[blockIdx.x];
        g_inv_deg[i] = 1.0f / (float)max(g_deg[i], 1);
    }
    if (i == 0) g_rowstart[NN] = EE;
}

__global__ void csr_fill_kernel(const void* __restrict__ ei) {
    int e = blockIdx.x * blockDim.x + threadIdx.x;
    if (e < EE) {
        int is64 = g_is64;
        int src = load_idx(ei, e, is64);
        int dst = load_idx(ei, (size_t)EE + e, is64);
        int pos = atomicAdd(&g_cursor[dst], 1);
        g_adj[g_rowstart[dst] + pos] = src;
    }
}

// ---------------- gather-mean: one warp per node, lane owns a float2 --------
// Unrolled x8 -> 8 row loads in flight (MLP 8) instead of a serial
// dynamic-bound loop (MLP~2) that made R5's fused kernel latency-bound.
__global__ void gather_kernel(int sel, const float* __restrict__ x) {
    int gtid = blockIdx.x * blockDim.x + threadIdx.x;
    int node = gtid >> 5;
    if (node >= NN) return;
    int lane = threadIdx.x & 31;

    const float2* hin = (sel == 0) ? (const float2*)x
                       : (sel == 1) ? (const float2*)g_h0 : (const float2*)g_h1;

    int rs = g_rowstart[node];
    int re = g_rowstart[node + 1];
    float ax = 0.f, ay = 0.f;
    int e = rs;
    for (; e + 8 <= re; e += 8) {
        int s0 = g_adj[e+0], s1 = g_adj[e+1], s2 = g_adj[e+2], s3 = g_adj[e+3];
        int s4 = g_adj[e+4], s5 = g_adj[e+5], s6 = g_adj[e+6], s7 = g_adj[e+7];
        float2 v0 = hin[(size_t)s0 * 32 + lane];
        float2 v1 = hin[(size_t)s1 * 32 + lane];
        float2 v2 = hin[(size_t)s2 * 32 + lane];
        float2 v3 = hin[(size_t)s3 * 32 + lane];
        float2 v4 = hin[(size_t)s4 * 32 + lane];
        float2 v5 = hin[(size_t)s5 * 32 + lane];
        float2 v6 = hin[(size_t)s6 * 32 + lane];
        float2 v7 = hin[(size_t)s7 * 32 + lane];
        ax += (v0.x + v1.x) + (v2.x + v3.x) + ((v4.x + v5.x) + (v6.x + v7.x));
        ay += (v0.y + v1.y) + (v2.y + v3.y) + ((v4.y + v5.y) + (v6.y + v7.y));
    }
    for (; e < re; e++) {
        int s = g_adj[e];
        float2 v = hin[(size_t)s * 32 + lane];
        ax += v.x; ay += v.y;
    }
    float inv = g_inv_deg[node];
    ((float2*)g_agg)[(size_t)node * 32 + lane] = make_float2(ax * inv, ay * inv);
}

// ---------------- linear: out = relu(agg@Wl + bl + h@Wr) --------------------
// 256 threads = 4 subs x 64 cols; 64 rows/block; no syncs in the row loop.
__global__ void linear_kernel(int sel, const float* __restrict__ x,
                              const float* __restrict__ Wl,
                              const float* __restrict__ bl,
                              const float* __restrict__ Wr) {
    __shared__ float sWl[DD * DD];
    __shared__ float sWr[DD * DD];
    __shared__ float sb[DD];

    const float4* hin  = (sel == 0) ? (const float4*)x
                        : (sel == 1) ? g_h0 : g_h1;
    float4*       hout = (sel == 0) ? g_h0 : ((sel == 1) ? g_h1 : g_h0);

    int tid = threadIdx.x;
    for (int i = tid; i < DD * DD; i += 256) { sWl[i] = Wl[i]; sWr[i] = Wr[i]; }
    if (tid < DD) sb[tid] = bl[tid];
    __syncthreads();

    int col = tid & 63;
    int sub = tid >> 6;
    int base = blockIdx.x * 64;

    for (int rr = sub; rr < 64; rr += 4) {
        int row = base + rr;
        if (row >= NN) break;
        const float4* ar = g_agg + (size_t)row * (DD / 4);
        const float4* hr = hin   + (size_t)row * (DD / 4);
        float accA = 0.f, accB = 0.f;
        #pragma unroll
        for (int k4 = 0; k4 < DD / 4; k4++) {
            float4 a4 = ar[k4];     // broadcast across the 64-col group (L1)
            float4 h4 = hr[k4];
            int k = k4 * 4;
            accA = fmaf(a4.x, sWl[(k+0) * DD + col], accA);
            accA = fmaf(a4.y, sWl[(k+1) * DD + col], accA);
            accA = fmaf(a4.z, sWl[(k+2) * DD + col], accA);
            accA = fmaf(a4.w, sWl[(k+3) * DD + col], accA);
            accB = fmaf(h4.x, sWr[(k+0) * DD + col], accB);
            accB = fmaf(h4.y, sWr[(k+1) * DD + col], accB);
            accB = fmaf(h4.z, sWr[(k+2) * DD + col], accB);
            accB = fmaf(h4.w, sWr[(k+3) * DD + col], accB);
        }
        ((float*)(hout + (size_t)row * (DD / 4)))[col] =
            fmaxf(accA + accB + sb[col], 0.f);
    }
}

// ---------------- global mean pool (batch sorted -> binary search) ----------
__global__ void pool_kernel() {
    int g = blockIdx.x;
    int col = threadIdx.x;
    int a = 0, b = NN;
    while (a < b) { int m = (a + b) >> 1; if (g_batch[m] < g) a = m + 1; else b = m; }
    int start = a;
    b = NN;
    while (a < b) { int m = (a + b) >> 1; if (g_batch[m] < g + 1) a = m + 1; else b = m; }
    int end = a;
    float acc = 0.f;
    const float* h = (const float*)g_h0;
    for (int n = start; n < end; n++) acc += h[(size_t)n * DD + col];
    g_pool[g * DD + col] = acc / fmaxf((float)(end - start), 1.f);
}

// ---------------- final MLP ----------------
__global__ void mlp_kernel(const float* __restrict__ l0W,
                           const float* __restrict__ l0b,
                           const float* __restrict__ outW,
                           const float* __restrict__ outb,
                           float* __restrict__ out) {
    __shared__ float sg[DD];
    __shared__ float sh[DD];
    int gi = blockIdx.x, t = threadIdx.x;
    sg[t] = g_pool[gi * DD + t];
    __syncthreads();
    float acc = l0b[t];
    #pragma unroll
    for (int k = 0; k < DD; k++) acc = fmaf(sg[k], l0W[k * DD + t], acc);
    sh[t] = fmaxf(acc, 0.f);
    __syncthreads();
    if (t < OUTC) {
        float a = outb[t];
        #pragma unroll
        for (int k = 0; k < DD; k++) a = fmaf(sh[k], outW[k * OUTC + t], a);
        out[gi * OUTC + t] = a;
    }
}

extern "C" void kernel_launch(void* const* d_in, const int* in_sizes, int n_in,
                              void* d_out, int out_size) {
    const float* x    = (const float*)d_in[0];
    const void*  ei   = d_in[1];
    const void*  bat  = d_in[2];
    const float* c_Wl[3] = { (const float*)d_in[3], (const float*)d_in[6], (const float*)d_in[9]  };
    const float* c_bl[3] = { (const float*)d_in[4], (const float*)d_in[7], (const float*)d_in[10] };
    const float* c_Wr[3] = { (const float*)d_in[5], (const float*)d_in[8], (const float*)d_in[11] };
    const float* l0W  = (const float*)d_in[12];
    const float* l0b  = (const float*)d_in[13];
    const float* outW = (const float*)d_in[14];
    const float* outb = (const float*)d_in[15];
    float* out = (float*)d_out;

    // ---- dtype detect + batch convert + CSR build ----
    detect_kernel<<<1, 1>>>((const unsigned int*)ei);
    prep_kernel<<<NB, 256>>>(bat);
    deg_kernel<<<(EE + 255) / 256, 256>>>(ei);
    scan_block_kernel<<<NB, 256>>>();
    scan_top_kernel<<<1, 512>>>();
    scan_add_kernel<<<NB, 256>>>();
    csr_fill_kernel<<<(EE + 255) / 256, 256>>>(ei);

    // ---- 3 SAGE layers: gather-mean then linear ----
    const int gather_blocks = (NN * 32 + 255) / 256;
    const int linear_blocks = (NN + 63) / 64;
    for (int l = 0; l < 3; l++) {
        gather_kernel<<<gather_blocks, 256>>>(l, x);
        linear_kernel<<<linear_blocks, 256>>>(l, x, c_Wl[l], c_bl[l], c_Wr[l]);
    }

    // ---- pooling + MLP ----
    pool_kernel<<<GG, DD>>>();
    mlp_kernel<<<GG, DD>>>(l0W, l0b, outW, outb, out);
}

// round 8
// speedup vs baseline: 2.1962x; 2.1962x over previous
#include <cuda_runtime.h>

#define NN 100000
#define EE 1600000
#define DD 64
#define GG 64
#define OUTC 10
#define NB ((NN + 255) / 256)   // 391 scan blocks

// ---- scratch ----
__device__ int    g_is64;
__device__ int    g_batch[NN];
__device__ int    g_deg[NN];
__device__ int    g_cursor[NN];
__device__ int    g_rowstart[NN + 1];
__device__ int    g_bsum[NB];
__device__ int    g_bsum_sc[NB];
__device__ int    g_adj[EE];
__device__ float  g_inv_deg[NN];
__device__ float4 g_agg[(size_t)NN * (DD / 4)];
__device__ float4 g_h0 [(size_t)NN * (DD / 4)];
__device__ float4 g_h1 [(size_t)NN * (DD / 4)];
__device__ float  g_pool[GG * DD];

// ---------------- dtype detection (int64-declared inputs usually arrive int32) --
__global__ void detect_kernel(const unsigned int* __restrict__ w) {
    int is64 = 1;
    for (int i = 0; i < 32; i++)
        if (w[2 * i + 1] != 0u) { is64 = 0; break; }
    g_is64 = is64;
}

__device__ __forceinline__ int load_idx(const void* p, size_t i, int is64) {
    return is64 ? (int)((const long long*)p)[i] : ((const int*)p)[i];
}

__global__ void prep_kernel(const void* __restrict__ bat) {
    int i = blockIdx.x * blockDim.x + threadIdx.x;
    if (i < NN) {
        g_batch[i]  = load_idx(bat, i, g_is64);
        g_deg[i]    = 0;
        g_cursor[i] = 0;
    }
}

// ---------------- CSR build ----------------
__global__ void deg_kernel(const void* __restrict__ ei) {
    int e = blockIdx.x * blockDim.x + threadIdx.x;
    if (e < EE) atomicAdd(&g_deg[load_idx(ei, (size_t)EE + e, g_is64)], 1);
}

__global__ void scan_block_kernel() {
    __shared__ int s[256];
    int tid = threadIdx.x;
    int i = blockIdx.x * 256 + tid;
    int v = (i < NN) ? g_deg[i] : 0;
    s[tid] = v;
    __syncthreads();
    #pragma unroll
    for (int off = 1; off < 256; off <<= 1) {
        int t = (tid >= off) ? s[tid - off] : 0;
        __syncthreads();
        s[tid] += t;
        __syncthreads();
    }
    if (i < NN) g_rowstart[i] = s[tid] - v;
    if (tid == 255) g_bsum[blockIdx.x] = s[255];
}

__global__ void scan_top_kernel() {
    __shared__ int s[512];
    int tid = threadIdx.x;
    int v = (tid < NB) ? g_bsum[tid] : 0;
    s[tid] = v;
    __syncthreads();
    #pragma unroll
    for (int off = 1; off < 512; off <<= 1) {
        int t = (tid >= off) ? s[tid - off] : 0;
        __syncthreads();
        s[tid] += t;
        __syncthreads();
    }
    if (tid < NB) g_bsum_sc[tid] = s[tid] - v;
}

__global__ void scan_add_kernel() {
    int i = blockIdx.x * 256 + threadIdx.x;
    if (i < NN) {
        g_rowstart[i] += g_bsum_sc[blockIdx.x];
        g_inv_deg[i] = 1.0f / (float)max(g_deg[i], 1);
    }
    if (i == 0) g_rowstart[NN] = EE;
}

__global__ void csr_fill_kernel(const void* __restrict__ ei) {
    int e = blockIdx.x * blockDim.x + threadIdx.x;
    if (e < EE) {
        int is64 = g_is64;
        int src = load_idx(ei, e, is64);
        int dst = load_idx(ei, (size_t)EE + e, is64);
        int pos = atomicAdd(&g_cursor[dst], 1);
        g_adj[g_rowstart[dst] + pos] = src;
    }
}

// ---------------- gather-mean: one warp per node, lane owns a float2, x8 MLP --
__global__ void gather_kernel(int sel, const float* __restrict__ x) {
    int gtid = blockIdx.x * blockDim.x + threadIdx.x;
    int node = gtid >> 5;
    if (node >= NN) return;
    int lane = threadIdx.x & 31;

    const float2* hin = (sel == 0) ? (const float2*)x
                       : (sel == 1) ? (const float2*)g_h0 : (const float2*)g_h1;

    int rs = g_rowstart[node];
    int re = g_rowstart[node + 1];
    float ax = 0.f, ay = 0.f;
    int e = rs;
    for (; e + 8 <= re; e += 8) {
        int s0 = g_adj[e+0], s1 = g_adj[e+1], s2 = g_adj[e+2], s3 = g_adj[e+3];
        int s4 = g_adj[e+4], s5 = g_adj[e+5], s6 = g_adj[e+6], s7 = g_adj[e+7];
        float2 v0 = hin[(size_t)s0 * 32 + lane];
        float2 v1 = hin[(size_t)s1 * 32 + lane];
        float2 v2 = hin[(size_t)s2 * 32 + lane];
        float2 v3 = hin[(size_t)s3 * 32 + lane];
        float2 v4 = hin[(size_t)s4 * 32 + lane];
        float2 v5 = hin[(size_t)s5 * 32 + lane];
        float2 v6 = hin[(size_t)s6 * 32 + lane];
        float2 v7 = hin[(size_t)s7 * 32 + lane];
        ax += (v0.x + v1.x) + (v2.x + v3.x) + ((v4.x + v5.x) + (v6.x + v7.x));
        ay += (v0.y + v1.y) + (v2.y + v3.y) + ((v4.y + v5.y) + (v6.y + v7.y));
    }
    for (; e < re; e++) {
        int s = g_adj[e];
        float2 v = hin[(size_t)s * 32 + lane];
        ax += v.x; ay += v.y;
    }
    float inv = g_inv_deg[node];
    ((float2*)g_agg)[(size_t)node * 32 + lane] = make_float2(ax * inv, ay * inv);
}

// ---------------- register-tiled linear ----------------
// out = relu([agg|h] @ [Wl;Wr] + bl); two k=64 passes over shared tiles.
// 256 threads = 16x16; each thread computes a 4x4 output tile.
// Per k: 1 LDS.128 (A) + 1 LDS.128 (W) feed 16 FMAs -> FMA-bound (fixes
// R5/R6's 1-LDS-per-FMA structure that capped FMA at ~25%).
__global__ void linear_kernel(int sel, const float* __restrict__ x,
                              const float* __restrict__ Wl,
                              const float* __restrict__ bl,
                              const float* __restrict__ Wr) {
    __shared__ __align__(16) float sA[DD][68];   // k-major, padded stride (68*4=272B, 16B-mult)
    __shared__ __align__(16) float sW[DD][DD];   // k-major (natural layout of W)
    __shared__ float sb[DD];

    const float* hin  = (sel == 0) ? x
                       : (sel == 1) ? (const float*)g_h0 : (const float*)g_h1;
    float*       hout = (sel == 0) ? (float*)g_h0
                       : (sel == 1) ? (float*)g_h1 : (float*)g_h0;

    int tid  = threadIdx.x;
    int base = blockIdx.x * 64;
    int tc = tid & 15;            // col group
    int tr = tid >> 4;            // row group
    if (tid < DD) sb[tid] = bl[tid];

    float acc[4][4];
    #pragma unroll
    for (int i = 0; i < 4; i++)
        #pragma unroll
        for (int j = 0; j < 4; j++) acc[i][j] = 0.f;

    int r_st   = tid >> 2;        // staging row 0..63
    int row_st = base + r_st;
    int k4b    = (tid & 3) * 4;   // staging k4 base

    #pragma unroll
    for (int pass = 0; pass < 2; pass++) {
        const float* A = (pass == 0) ? (const float*)g_agg : hin;
        const float* W = (pass == 0) ? Wl : Wr;
        // stage W [64][64]
        for (int i = tid; i < DD * DD; i += 256) sW[i >> 6][i & 63] = W[i];
        // stage A transposed: coalesced float4 loads, scattered smem stores
        #pragma unroll
        for (int j = 0; j < 4; j++) {
            int k4 = k4b + j;
            float4 v = make_float4(0.f, 0.f, 0.f, 0.f);
            if (row_st < NN) v = ((const float4*)A)[(size_t)row_st * (DD/4) + k4];
            sA[k4 * 4 + 0][r_st] = v.x;
            sA[k4 * 4 + 1][r_st] = v.y;
            sA[k4 * 4 + 2][r_st] = v.z;
            sA[k4 * 4 + 3][r_st] = v.w;
        }
        __syncthreads();
        #pragma unroll 8
        for (int k = 0; k < DD; k++) {
            float4 a4 = *(const float4*)&sA[k][tr * 4];
            float4 w4 = *(const float4*)&sW[k][tc * 4];
            float av[4] = { a4.x, a4.y, a4.z, a4.w };
            float wv[4] = { w4.x, w4.y, w4.z, w4.w };
            #pragma unroll
            for (int i = 0; i < 4; i++)
                #pragma unroll
                for (int j = 0; j < 4; j++)
                    acc[i][j] = fmaf(av[i], wv[j], acc[i][j]);
        }
        __syncthreads();
    }

    // epilogue: bias + relu, float4 stores
    #pragma unroll
    for (int i = 0; i < 4; i++) {
        int row = base + tr * 4 + i;
        if (row < NN) {
            float4 o;
            o.x = fmaxf(acc[i][0] + sb[tc * 4 + 0], 0.f);
            o.y = fmaxf(acc[i][1] + sb[tc * 4 + 1], 0.f);
            o.z = fmaxf(acc[i][2] + sb[tc * 4 + 2], 0.f);
            o.w = fmaxf(acc[i][3] + sb[tc * 4 + 3], 0.f);
            *(float4*)&hout[(size_t)row * DD + tc * 4] = o;
        }
    }
}

// ---------------- global mean pool ----------------
__global__ void pool_kernel() {
    int g = blockIdx.x;
    int col = threadIdx.x;
    int a = 0, b = NN;
    while (a < b) { int m = (a + b) >> 1; if (g_batch[m] < g) a = m + 1; else b = m; }
    int start = a;
    b = NN;
    while (a < b) { int m = (a + b) >> 1; if (g_batch[m] < g + 1) a = m + 1; else b = m; }
    int end = a;
    float acc = 0.f;
    const float* h = (const float*)g_h0;
    for (int n = start; n < end; n++) acc += h[(size_t)n * DD + col];
    g_pool[g * DD + col] = acc / fmaxf((float)(end - start), 1.f);
}

// ---------------- final MLP ----------------
__global__ void mlp_kernel(const float* __restrict__ l0W,
                           const float* __restrict__ l0b,
                           const float* __restrict__ outW,
                           const float* __restrict__ outb,
                           float* __restrict__ out) {
    __shared__ float sg[DD];
    __shared__ float sh[DD];
    int gi = blockIdx.x, t = threadIdx.x;
    sg[t] = g_pool[gi * DD + t];
    __syncthreads();
    float acc = l0b[t];
    #pragma unroll
    for (int k = 0; k < DD; k++) acc = fmaf(sg[k], l0W[k * DD + t], acc);
    sh[t] = fmaxf(acc, 0.f);
    __syncthreads();
    if (t < OUTC) {
        float a = outb[t];
        #pragma unroll
        for (int k = 0; k < DD; k++) a = fmaf(sh[k], outW[k * OUTC + t], a);
        out[gi * OUTC + t] = a;
    }
}

extern "C" void kernel_launch(void* const* d_in, const int* in_sizes, int n_in,
                              void* d_out, int out_size) {
    const float* x    = (const float*)d_in[0];
    const void*  ei   = d_in[1];
    const void*  bat  = d_in[2];
    const float* c_Wl[3] = { (const float*)d_in[3], (const float*)d_in[6], (const float*)d_in[9]  };
    const float* c_bl[3] = { (const float*)d_in[4], (const float*)d_in[7], (const float*)d_in[10] };
    const float* c_Wr[3] = { (const float*)d_in[5], (const float*)d_in[8], (const float*)d_in[11] };
    const float* l0W  = (const float*)d_in[12];
    const float* l0b  = (const float*)d_in[13];
    const float* outW = (const float*)d_in[14];
    const float* outb = (const float*)d_in[15];
    float* out = (float*)d_out;

    // ---- dtype detect + batch convert + CSR build ----
    detect_kernel<<<1, 1>>>((const unsigned int*)ei);
    prep_kernel<<<NB, 256>>>(bat);
    deg_kernel<<<(EE + 255) / 256, 256>>>(ei);
    scan_block_kernel<<<NB, 256>>>();
    scan_top_kernel<<<1, 512>>>();
    scan_add_kernel<<<NB, 256>>>();
    csr_fill_kernel<<<(EE + 255) / 256, 256>>>(ei);

    // ---- 3 SAGE layers ----
    const int gather_blocks = (NN * 32 + 255) / 256;
    const int linear_blocks = (NN + 63) / 64;
    for (int l = 0; l < 3; l++) {
        gather_kernel<<<gather_blocks, 256>>>(l, x);
        linear_kernel<<<linear_blocks, 256>>>(l, x, c_Wl[l], c_bl[l], c_Wr[l]);
    }

    // ---- pooling + MLP ----
    pool_kernel<<<GG, DD>>>();
    mlp_kernel<<<GG, DD>>>(l0W, l0b, outW, outb, out);
}